// round 4
// baseline (speedup 1.0000x reference)
#include <cuda_runtime.h>
#include <math.h>

#define D 128
#define HD 1024
#define H 8
#define NCIR 585
#define NDIS 88
#define ECC 20000
#define EDD 3000
#define NB 148

__device__ __align__(16) float g_scratch[1720000];
__device__ unsigned g_cnt = 0;
__device__ volatile unsigned g_sense = 0;

struct BP {
    const float *x, *mat;
    const int *edges;
    const float *gb1, *ab, *gb2, *cw, *cb;
    const float *asrc, *adst, *aedge, *awe;
    const float *gw1, *aw, *gw2;
    float *fea;
    int N, E;
    float *ew, *deg, *h, *f1, *h2, *an_src, *an_dst, *att, *f2, *cvec, *ewsum;
    int *cnt, *rowptr, *cursor, *eid;
};
struct Pair { BP b[2]; };

static inline int cdiv(int a, int b) { return (a + b - 1) / b; }
static inline int pad4(int n) { return (n + 3) & ~3; }

// ---------------- device-wide barrier ----------------
__device__ __forceinline__ void gsync(unsigned* s_sense) {
    __syncthreads();
    __threadfence();                 // release: drain this thread's writes to L2
    __syncthreads();
    if (threadIdx.x == 0) {
        unsigned ns = *s_sense ^ 1u;
        *s_sense = ns;
        if (atomicAdd(&g_cnt, 1u) == NB - 1) {
            g_cnt = 0;
            __threadfence();
            g_sense = ns;
        } else {
            while (g_sense != ns) __nanosleep(64);
        }
        __threadfence();             // acquire: CCTL.IVALL — invalidate stale L1
    }
    __syncthreads();
}

// ---------------- edge pass 1 ----------------
__device__ void edge1_branch(const BP& bp, int gid) {
    int Er = (bp.E + 31) & ~31;
    for (int e = gid; e < Er; e += NB * 256) {
        float w = 0.f;
        if (e < bp.E) {
            int s = bp.edges[e], d = bp.edges[bp.E + e];
            w = bp.mat[s * bp.N + d];
            bp.ew[e] = w;
            atomicAdd(bp.deg + d, w);
            atomicAdd(bp.cnt + d, 1);
        }
        float ws = w;
        #pragma unroll
        for (int o = 16; o; o >>= 1) ws += __shfl_down_sync(0xffffffffu, ws, o);
        if ((threadIdx.x & 31) == 0 && ws != 0.f) atomicAdd(bp.ewsum, ws);
    }
}

// ---------------- scan (one block per branch) ----------------
__device__ void scan_branch(const BP& bp, float* sbuf, int tid) {
    int* sc = (int*)sbuf;
    int base = tid * 4;
    int v[4]; int s = 0;
    #pragma unroll
    for (int q = 0; q < 4; q++) {
        v[q] = (base + q < bp.N) ? bp.cnt[base + q] : 0;
        s += v[q];
    }
    sc[tid] = s; __syncthreads();
    #pragma unroll
    for (int off = 1; off < 256; off <<= 1) {
        int t2 = (tid >= off) ? sc[tid - off] : 0;
        __syncthreads();
        sc[tid] += t2;
        __syncthreads();
    }
    int run = sc[tid] - s;   // exclusive prefix
    #pragma unroll
    for (int q = 0; q < 4; q++) {
        run += v[q];
        if (base + q < bp.N) {
            bp.rowptr[base + q + 1] = run;
            bp.cursor[base + q] = run - v[q];
            bp.deg[base + q] = rsqrtf(bp.deg[base + q]);
        }
    }
    if (tid == 0) bp.rowptr[0] = 0;
    __syncthreads();
}

// ---------------- edge pass 2: CSR placement ----------------
__device__ void edge2_branch(const BP& bp, int gid) {
    for (int e = gid; e < bp.E; e += NB * 256) {
        int d = bp.edges[bp.E + e];
        int pos = atomicAdd(bp.cursor + d, 1);
        bp.eid[pos] = e;
    }
}

// ---------------- tiled GEMM: C = A[M,128] @ W[128,ncols] ----------------
__device__ void gemm_phase(float* sA, int tid,
                           const float* A0, const float* W0, float* C0, int M0,
                           const float* A1, const float* W1, float* C1, int M1,
                           int ncols) {
    int cbn = ncols >> 7;
    int t0 = ((M0 + 15) >> 4) * cbn;
    int t1 = ((M1 + 15) >> 4) * cbn;
    for (int t = blockIdx.x; t < t0 + t1; t += NB) {
        int br = t >= t0;
        int tt = br ? t - t0 : t;
        const float* A = br ? A1 : A0;
        const float* W = br ? W1 : W0;
        float* C = br ? C1 : C0;
        int M = br ? M1 : M0;
        int rb = (tt / cbn) << 4;
        int cb = (tt % cbn) << 7;
        #pragma unroll
        for (int q = 0; q < 8; q++) {
            int idx = q * 256 + tid;
            int r = idx >> 7, k = idx & 127;
            sA[idx] = (rb + r < M) ? A[(rb + r) * 128 + k] : 0.f;
        }
        __syncthreads();
        int col = cb + (tid & 127);
        int r0 = (tid >> 7) << 3;
        float acc[8] = {0.f, 0.f, 0.f, 0.f, 0.f, 0.f, 0.f, 0.f};
        #pragma unroll 4
        for (int k = 0; k < 128; k++) {
            float w = W[k * ncols + col];
            #pragma unroll
            for (int r = 0; r < 8; r++) acc[r] = fmaf(sA[(r0 + r) * 128 + k], w, acc[r]);
        }
        #pragma unroll
        for (int r = 0; r < 8; r++)
            if (rb + r0 + r < M) C[(rb + r0 + r) * ncols + col] = acc[r];
        __syncthreads();
    }
}

// ---------------- GCN gather ----------------
__device__ void gather_phase(const Pair& P, float* sbuf, int tid, int which) {
    int* ssrc = (int*)sbuf;
    float* snorm = sbuf + 128;
    int NT = P.b[0].N + P.b[1].N;
    for (int task = blockIdx.x; task < NT; task += NB) {
        int br = task >= P.b[0].N;
        const BP& bp = P.b[br];
        int d = br ? task - P.b[0].N : task;
        int j = tid & 127;
        const float* bias = which ? bp.gb2 : bp.gb1;
        float* out = which ? bp.f2 : bp.f1;
        const float* h = bp.h;
        float dd = bp.deg[d];
        float acc = fmaf(h[d * D + j], dd * dd, bias[j]);
        int rp = bp.rowptr[d], re = bp.rowptr[d + 1];
        for (int base = rp; base < re; base += 128) {
            int c = base + tid;
            if (tid < 128 && c < re) {
                int e = bp.eid[c];
                int s = bp.edges[e];
                ssrc[tid] = s;
                snorm[tid] = bp.deg[s] * bp.ew[e] * dd;
            }
            __syncthreads();
            int cnt = min(128, re - base);
            if (tid < 128)
                for (int t = 0; t < cnt; t++)
                    acc = fmaf(h[ssrc[t] * D + j], snorm[t], acc);
            __syncthreads();
        }
        if (tid < 128) out[d * D + j] = fmaxf(acc, 0.f);
        __syncthreads();
    }
}

// ---------------- attention node dots + cvec ----------------
__device__ void attn_phase(const Pair& P, int tid) {
    int lane = tid & 31;
    int n0 = P.b[0].N, n1 = P.b[1].N;
    int wtot = (n0 + n1) * H + 16;
    for (int gw0 = blockIdx.x * 8 + (tid >> 5); gw0 < wtot; gw0 += NB * 8) {
        int gw = gw0;
        int br, n = 0, hh;
        bool cv = false;
        if (gw < n0 * H) { br = 0; n = gw / H; hh = gw % H; }
        else if (gw < (n0 + n1) * H) { gw -= n0 * H; br = 1; n = gw / H; hh = gw % H; }
        else {
            gw -= (n0 + n1) * H;
            br = gw >= H; hh = gw & 7; cv = true;
        }
        const BP& bp = P.b[br];
        if (cv) {
            float4 a = ((const float4*)bp.awe)[hh * 32 + lane];
            float4 b = ((const float4*)bp.aedge)[hh * 32 + lane];
            float s = a.x * b.x + a.y * b.y + a.z * b.z + a.w * b.w;
            #pragma unroll
            for (int o = 16; o; o >>= 1) s += __shfl_down_sync(0xffffffffu, s, o);
            if (lane == 0) bp.cvec[hh] = s;
            continue;
        }
        float4 v = ((const float4*)(bp.h2 + n * HD + hh * D))[lane];
        float4 as = ((const float4*)(bp.asrc + hh * D))[lane];
        float4 ad = ((const float4*)(bp.adst + hh * D))[lane];
        float s1 = v.x * as.x + v.y * as.y + v.z * as.z + v.w * as.w;
        float s2 = v.x * ad.x + v.y * ad.y + v.z * ad.z + v.w * ad.w;
        #pragma unroll
        for (int o = 16; o; o >>= 1) {
            s1 += __shfl_down_sync(0xffffffffu, s1, o);
            s2 += __shfl_down_sync(0xffffffffu, s2, o);
        }
        if (lane == 0) { bp.an_src[n * H + hh] = s1; bp.an_dst[n * H + hh] = s2; }
    }
}

// ---------------- fused GAT ----------------
#define CH 128
__device__ void gat_phase(const Pair& P, float* sbuf, int tid) {
    int lane = tid & 31, wid = tid >> 5;
    int* ssrc  = (int*)sbuf;           // 128
    float* sew = sbuf + 128;           // 128
    float* scoef = sbuf + 256;         // 8*128
    float* sm   = sbuf + 1280;         // 8
    float* sden = sbuf + 1288;         // 8
    float* sc   = sbuf + 1296;         // 8
    float* sred = sbuf + 1304;         // 128
    int NT = P.b[0].N + P.b[1].N;
    for (int task = blockIdx.x; task < NT; task += NB) {
        int br = task >= P.b[0].N;
        const BP& bp = P.b[br];
        int d = br ? task - P.b[0].N : task;
        if (tid < 8) sc[tid] = bp.cvec[tid];
        float meanw = bp.ewsum[0] / (float)bp.E;
        int rp = bp.rowptr[d];
        int deg = bp.rowptr[d + 1] - rp;
        int total = deg + 1;
        __syncthreads();
        float adst = bp.an_dst[d * H + wid];
        float chh = sc[wid];

        float m = -INFINITY, den = 0.f;
        for (int base = 0; base < total; base += CH) {
            int cnt = min(CH, total - base);
            if (tid < CH && base + tid < total) {
                int c = base + tid;
                if (c < deg) {
                    int e = bp.eid[rp + c];
                    ssrc[tid] = bp.edges[e];
                    sew[tid] = bp.ew[e];
                } else { ssrc[tid] = d; sew[tid] = meanw; }
            }
            __syncthreads();
            float lg[4];
            int have = 0;
            float cm = -INFINITY;
            for (int c = lane; c < cnt; c += 32) {
                float l = bp.an_src[ssrc[c] * H + wid] + adst + sew[c] * chh;
                l = (l >= 0.f) ? l : 0.2f * l;
                lg[have++] = l;
                cm = fmaxf(cm, l);
            }
            #pragma unroll
            for (int o = 16; o; o >>= 1) cm = fmaxf(cm, __shfl_xor_sync(0xffffffffu, cm, o));
            float newm = fmaxf(m, cm);
            float ls = 0.f;
            for (int q = 0; q < have; q++) ls += __expf(lg[q] - newm);
            #pragma unroll
            for (int o = 16; o; o >>= 1) ls += __shfl_xor_sync(0xffffffffu, ls, o);
            den = den * __expf(m - newm) + ls;
            m = newm;
            __syncthreads();
        }
        if (lane == 0) { sm[wid] = m; sden[wid] = den + 1e-16f; }
        __syncthreads();

        int j = tid & 127;
        int hbase = (tid >> 7) * 4;
        float acc0 = 0.f, acc1 = 0.f, acc2 = 0.f, acc3 = 0.f;
        for (int base = 0; base < total; base += CH) {
            int cnt = min(CH, total - base);
            if (tid < CH && base + tid < total) {
                int c = base + tid;
                if (c < deg) {
                    int e = bp.eid[rp + c];
                    ssrc[tid] = bp.edges[e];
                    sew[tid] = bp.ew[e];
                } else { ssrc[tid] = d; sew[tid] = meanw; }
            }
            __syncthreads();
            for (int c = lane; c < cnt; c += 32) {
                float l = bp.an_src[ssrc[c] * H + wid] + adst + sew[c] * chh;
                l = (l >= 0.f) ? l : 0.2f * l;
                scoef[wid * CH + c] = __expf(l - sm[wid]) / sden[wid];
            }
            __syncthreads();
            for (int c = 0; c < cnt; c++) {
                const float* hr = bp.h2 + ssrc[c] * HD + hbase * D + j;
                acc0 = fmaf(hr[0],     scoef[(hbase + 0) * CH + c], acc0);
                acc1 = fmaf(hr[D],     scoef[(hbase + 1) * CH + c], acc1);
                acc2 = fmaf(hr[2 * D], scoef[(hbase + 2) * CH + c], acc2);
                acc3 = fmaf(hr[3 * D], scoef[(hbase + 3) * CH + c], acc3);
            }
            __syncthreads();
        }
        float part = acc0 + acc1 + acc2 + acc3;
        if (tid < 128) sred[j] = part;
        __syncthreads();
        if (tid >= 128)
            bp.att[d * D + j] = fmaxf(fmaf(sred[j] + part, 0.125f, bp.ab[j]), 0.f);
        __syncthreads();
    }
}

// ---------------- CNN head ----------------
__device__ void cnn_phase(const Pair& P, float* sA, int tid) {
    int t0 = ((P.b[0].N + 15) >> 4) * 2;
    int t1 = ((P.b[1].N + 15) >> 4) * 2;
    for (int t = blockIdx.x; t < t0 + t1; t += NB) {
        int br = t >= t0;
        const BP& bp = P.b[br];
        int tt = br ? t - t0 : t;
        int rb = (tt >> 1) << 4;
        int cb = (tt & 1) << 7;
        #pragma unroll
        for (int q = 0; q < 16; q++) {
            int idx = q * 256 + tid;
            int r = idx >> 8, k = idx & 255;
            int n = rb + r;
            float v = 0.f;
            if (n < bp.N) v = (k < 128) ? bp.f1[n * 128 + k] : bp.f2[n * 128 + k - 128];
            sA[idx] = v;
        }
        __syncthreads();
        int o = cb + (tid & 127);
        int r0 = (tid >> 7) << 3;
        float bo = bp.cb[o];
        float acc[8];
        #pragma unroll
        for (int r = 0; r < 8; r++) acc[r] = bo;
        const float* w = bp.cw + o * 256;
        #pragma unroll 4
        for (int k = 0; k < 256; k++) {
            float wv = w[k];
            #pragma unroll
            for (int r = 0; r < 8; r++) acc[r] = fmaf(sA[(r0 + r) * 256 + k], wv, acc[r]);
        }
        #pragma unroll
        for (int r = 0; r < 8; r++)
            if (rb + r0 + r < bp.N) bp.fea[(rb + r0 + r) * 256 + o] = acc[r];
        __syncthreads();
    }
}

// ---------------- final matmul (split-K) ----------------
__device__ void final_phase(const float* cir, const float* dis, float* out,
                            float* sA, int tid) {
    for (int t = blockIdx.x; t < (NCIR + 15) / 16; t += NB) {
        int ib = t * 16;
        #pragma unroll
        for (int q = 0; q < 16; q++) {
            int idx = q * 256 + tid;
            int i = ib + (idx >> 8);
            sA[idx] = (i < NCIR) ? cir[i * 256 + (idx & 255)] : 0.f;
        }
        __syncthreads();
        int j = tid & 127;
        int half = tid >> 7;
        float acc[16];
        #pragma unroll
        for (int r = 0; r < 16; r++) acc[r] = 0.f;
        if (j < NDIS) {
            const float* dr = dis + j * 256 + half * 128;
            #pragma unroll 4
            for (int k = 0; k < 128; k++) {
                float dv = dr[k];
                #pragma unroll
                for (int r = 0; r < 16; r++)
                    acc[r] = fmaf(sA[r * 256 + half * 128 + k], dv, acc[r]);
            }
        }
        __syncthreads();
        if (half == 1 && j < NDIS) {
            #pragma unroll
            for (int r = 0; r < 16; r++) sA[j * 16 + r] = acc[r];
        }
        __syncthreads();
        if (half == 0 && j < NDIS) {
            #pragma unroll
            for (int r = 0; r < 16; r++)
                if (ib + r < NCIR) out[(ib + r) * NDIS + j] = acc[r] + sA[j * 16 + r];
        }
        __syncthreads();
    }
}

// ---------------- mega kernel ----------------
__global__ __launch_bounds__(256, 1) void k_mega(Pair P, float* out) {
    __shared__ float sbuf[4160];
    __shared__ unsigned s_sense;
    const int tid = threadIdx.x;
    const int gid = blockIdx.x * 256 + tid;
    if (tid == 0) s_sense = g_sense;
    __syncthreads();

    const BP& b0 = P.b[0];
    const BP& b1 = P.b[1];

    // A: init + GEMM1 (h = x @ W1)
    for (int i = gid; i < 1024; i += NB * 256) {
        if (i < b0.N) { b0.deg[i] = 1.f; b0.cnt[i] = 0; }
        if (i < b1.N) { b1.deg[i] = 1.f; b1.cnt[i] = 0; }
        if (i == 0) { b0.ewsum[0] = 0.f; b1.ewsum[0] = 0.f; }
    }
    gemm_phase(sbuf, tid, b0.x, b0.gw1, b0.h, b0.N, b1.x, b1.gw1, b1.h, b1.N, 128);
    gsync(&s_sense);

    // B: edge gather + degree + histogram
    edge1_branch(b0, gid);
    edge1_branch(b1, gid);
    gsync(&s_sense);

    // C: scan -> rowptr/cursor, deg -> rsqrt
    if (blockIdx.x < 2) scan_branch(P.b[blockIdx.x], sbuf, tid);
    gsync(&s_sense);

    // D: CSR placement
    edge2_branch(b0, gid);
    edge2_branch(b1, gid);
    gsync(&s_sense);

    // E: GCN1 gather -> f1
    gather_phase(P, sbuf, tid, 0);
    gsync(&s_sense);

    // F: GEMM2 (h2 = f1 @ aw)
    gemm_phase(sbuf, tid, b0.f1, b0.aw, b0.h2, b0.N, b1.f1, b1.aw, b1.h2, b1.N, HD);
    gsync(&s_sense);

    // G: attention dots + cvec
    attn_phase(P, tid);
    gsync(&s_sense);

    // H: fused GAT -> att
    gat_phase(P, sbuf, tid);
    gsync(&s_sense);

    // I: GEMM3 (h = att @ W2)
    gemm_phase(sbuf, tid, b0.att, b0.gw2, b0.h, b0.N, b1.att, b1.gw2, b1.h, b1.N, 128);
    gsync(&s_sense);

    // J: GCN2 gather -> f2
    gather_phase(P, sbuf, tid, 1);
    gsync(&s_sense);

    // K: CNN heads -> fea
    cnn_phase(P, sbuf, tid);
    gsync(&s_sense);

    // L: final matmul
    final_phase(b0.fea, b1.fea, out, sbuf, tid);
}

// -------------------- host --------------------
static void fill_bp(BP& bp, const float* x, const float* mat, const int* edges,
                    const float* gw1, const float* gb1,
                    const float* aw, const float* asrc, const float* adst,
                    const float* aedge, const float* awe, const float* ab,
                    const float* gw2, const float* gb2,
                    const float* cw, const float* cb,
                    float* fea, int N, int E, float*& S) {
    bp.x = x; bp.mat = mat; bp.edges = edges;
    bp.gw1 = gw1; bp.gb1 = gb1; bp.aw = aw;
    bp.asrc = asrc; bp.adst = adst; bp.aedge = aedge;
    bp.awe = awe; bp.ab = ab; bp.gw2 = gw2; bp.gb2 = gb2;
    bp.cw = cw; bp.cb = cb;
    bp.fea = fea; bp.N = N; bp.E = E;
    bp.ew = S;        S += pad4(E);
    bp.deg = S;       S += pad4(N);
    bp.h = S;         S += pad4(N * D);
    bp.f1 = S;        S += pad4(N * D);
    bp.h2 = S;        S += pad4(N * HD);
    bp.an_src = S;    S += pad4(N * H);
    bp.an_dst = S;    S += pad4(N * H);
    bp.att = S;       S += pad4(N * D);
    bp.f2 = S;        S += pad4(N * D);
    bp.cvec = S;      S += 8;
    bp.ewsum = S;     S += 8;
    bp.cnt = (int*)S;    S += pad4(N);
    bp.rowptr = (int*)S; S += pad4(N + 1);
    bp.cursor = (int*)S; S += pad4(N);
    bp.eid = (int*)S;    S += pad4(E);
}

extern "C" void kernel_launch(void* const* d_in, const int* in_sizes, int n_in,
                              void* d_out, int out_size) {
    float* S = nullptr;
    cudaGetSymbolAddress((void**)&S, g_scratch);

    const float* in_f[28];
    for (int i = 0; i < 28; i++) in_f[i] = (const float*)d_in[i];
    const int* cc_edges = (const int*)d_in[28];
    const int* dd_edges = (const int*)d_in[29];

    float* out = (float*)d_out;
    float* cirfea = out + NCIR * NDIS;
    float* disfea = cirfea + NCIR * 256;

    Pair P;
    float* cur = S;
    fill_bp(P.b[0], in_f[0], in_f[2], cc_edges,
            in_f[4], in_f[5], in_f[6], in_f[7], in_f[8], in_f[9], in_f[10], in_f[11],
            in_f[12], in_f[13], in_f[24], in_f[25], cirfea, NCIR, ECC, cur);
    fill_bp(P.b[1], in_f[1], in_f[3], dd_edges,
            in_f[14], in_f[15], in_f[16], in_f[17], in_f[18], in_f[19], in_f[20], in_f[21],
            in_f[22], in_f[23], in_f[26], in_f[27], disfea, NDIS, EDD, cur);

    k_mega<<<NB, 256>>>(P, out);
}